// round 1
// baseline (speedup 1.0000x reference)
#include <cuda_runtime.h>
#include <math.h>
#include <float.h>

#define NB 256
#define NT 512
#define NF 1024
#define NS 48
#define NM (NB*NT)

// ---------------- scratch (device globals; no allocations allowed) ----------
__device__ float g_mean[NB*NF];
__device__ float g_rstd[NB*NF];
__device__ float g_sf[(size_t)NM*NS];   // clipped state features, row-major [M][48]

// ---------------- pass 1: per-(b,f) mean / rstd over T ----------------------
__global__ __launch_bounds__(256) void stats_kernel(const float* __restrict__ feat) {
    int b = blockIdx.y;
    int f = blockIdx.x * 256 + threadIdx.x;
    const float* p = feat + (size_t)b * NT * NF + f;
    float s0 = 0.f, s1 = 0.f;
#pragma unroll 8
    for (int t = 0; t < NT; t++) {
        float x = p[(size_t)t * NF];
        s0 += x;
        s1 = fmaf(x, x, s1);
    }
    float mean = s0 * (1.0f / NT);
    float var  = (s1 - s0 * s0 * (1.0f / NT)) * (1.0f / (NT - 1));
    var = fmaxf(var, 0.f);
    float sd = sqrtf(var);
    float rs = (sd == 0.f) ? 1.f : 1.f / sd;
    g_mean[b * NF + f] = mean;
    g_rstd[b * NF + f] = rs;
}

// ---------------- pass 2: fused normalize + GEMM (fp32x2 packed FMA) --------
// CTA: 128 rows x 48 cols, 128 threads, thread tile 8 rows x 6 cols
// (accumulated as 4 row-pairs x 6 cols in packed f32x2 registers).
#define KC 32
#define AS_STRIDE 130   // even (8B-aligned LDS.64), odd/2 for bank spread

__global__ __launch_bounds__(128) void gemm_kernel(const float* __restrict__ feat,
                                                   const float* __restrict__ sw,
                                                   const float* __restrict__ sb) {
    __shared__ float  As[KC][AS_STRIDE];   // transposed: As[k][row]
    __shared__ float2 Ws2[KC][49];         // duplicated weight pairs (w,w)

    int tid = threadIdx.x;
    int row_base = blockIdx.x * 128;       // 128 | 512 -> single b per CTA
    int b = row_base / NT;

    int r0 = (tid >> 3) * 8;               // 0..120
    int c0 = (tid & 7) * 6;                // 0..42

    unsigned long long acc[4][6];
#pragma unroll
    for (int i = 0; i < 4; i++)
#pragma unroll
        for (int c = 0; c < 6; c++) acc[i][c] = 0ULL;

    int lf    = (tid & 7) * 4;             // f_local of this thread's float4 loads
    int lrow0 = tid >> 3;                  // 0..15

    for (int kc = 0; kc < NF; kc += KC) {
        // stats for this thread's 4 f-columns (reused across all 8 row iters)
        float4 m4 = *(const float4*)(g_mean + b * NF + kc + lf);
        float4 r4 = *(const float4*)(g_rstd + b * NF + kc + lf);

        // load + normalize + clip A tile, store transposed
#pragma unroll
        for (int it = 0; it < 8; it++) {
            int row = lrow0 + it * 16;
            float4 x = *(const float4*)(feat + (size_t)(row_base + row) * NF + kc + lf);
            float n0 = fminf(fmaxf((x.x - m4.x) * r4.x, -10.f), 10.f);
            float n1 = fminf(fmaxf((x.y - m4.y) * r4.y, -10.f), 10.f);
            float n2 = fminf(fmaxf((x.z - m4.z) * r4.z, -10.f), 10.f);
            float n3 = fminf(fmaxf((x.w - m4.w) * r4.w, -10.f), 10.f);
            As[lf + 0][row] = n0;
            As[lf + 1][row] = n1;
            As[lf + 2][row] = n2;
            As[lf + 3][row] = n3;
        }
        // load W tile duplicated into float2 pairs
#pragma unroll
        for (int it = 0; it < 12; it++) {
            int idx = it * 128 + tid;
            int c  = idx >> 5;             // 0..47
            int fl = idx & 31;             // 0..31
            float w = sw[c * NF + kc + fl];
            Ws2[fl][c] = make_float2(w, w);
        }
        __syncthreads();

#pragma unroll
        for (int k = 0; k < KC; k++) {
            unsigned long long a2[4], w2[6];
#pragma unroll
            for (int i = 0; i < 4; i++)
                a2[i] = *(const unsigned long long*)&As[k][r0 + 2 * i];
#pragma unroll
            for (int c = 0; c < 6; c++)
                w2[c] = *(const unsigned long long*)&Ws2[k][c0 + c];
#pragma unroll
            for (int i = 0; i < 4; i++)
#pragma unroll
                for (int c = 0; c < 6; c++)
                    asm("fma.rn.f32x2 %0, %1, %2, %0;"
                        : "+l"(acc[i][c]) : "l"(a2[i]), "l"(w2[c]));
        }
        __syncthreads();
    }

    // epilogue: + bias, clip to [-5,5], store sf
#pragma unroll
    for (int c = 0; c < 6; c++) {
        float bias = sb[c0 + c];
#pragma unroll
        for (int i = 0; i < 4; i++) {
            unsigned long long v = acc[i][c];
            float lo = __uint_as_float((unsigned)(v & 0xffffffffu));
            float hi = __uint_as_float((unsigned)(v >> 32));
            lo = fminf(fmaxf(lo + bias, -5.f), 5.f);
            hi = fminf(fmaxf(hi + bias, -5.f), 5.f);
            int row = row_base + r0 + 2 * i;
            g_sf[(size_t)row * NS + c0 + c]       = lo;
            g_sf[(size_t)(row + 1) * NS + c0 + c] = hi;
        }
    }
}

// ---------------- pass 3: forward recursion ---------------------------------
// logsumexp_j(a_j + T_jk) = m + log( sum_j exp(a_j - m) * E_jk ),
// E = exp(clip(trans)) precomputed in registers (48 per thread = column k).
__global__ __launch_bounds__(64) void crf_kernel(const float* __restrict__ tw,
                                                 const float* __restrict__ tb,
                                                 float* __restrict__ out) {
    int b   = blockIdx.x;
    int tid = threadIdx.x;
    int k   = tid;
    bool act = (k < NS);
    int wid = tid >> 5, lane = tid & 31;

    __shared__ float sh_p[2][NS];
    __shared__ float sh_m[2][2];

    float E[NS];
    if (act) {
#pragma unroll
        for (int j = 0; j < NS; j++) {
            float tv = tw[j * NS + k] + tb[j * NS + k];
            tv = fminf(fmaxf(tv, -5.f), 5.f);
            E[j] = expf(tv);
        }
    }

    float*       alpha_out = out + NB + (size_t)b * NT * NS;
    const float* sfb       = g_sf + (size_t)b * NT * NS;

    float a = act ? sfb[k] : -FLT_MAX;
    if (act) alpha_out[k] = a;

    for (int t = 1; t < NT; t++) {
        int buf = t & 1;
        float sf_t = act ? __ldg(&sfb[t * NS + k]) : 0.f;  // prefetch early

        float v = act ? a : -FLT_MAX;
#pragma unroll
        for (int o = 16; o > 0; o >>= 1)
            v = fmaxf(v, __shfl_xor_sync(0xffffffffu, v, o));
        if (lane == 0) sh_m[buf][wid] = v;
        __syncthreads();
        float m = fmaxf(sh_m[buf][0], sh_m[buf][1]);
        if (act) sh_p[buf][k] = expf(a - m);
        __syncthreads();

        if (act) {
            float s0 = 0.f, s1 = 0.f, s2 = 0.f, s3 = 0.f;
#pragma unroll
            for (int j = 0; j < NS; j += 4) {
                float4 p4 = *(const float4*)&sh_p[buf][j];
                s0 = fmaf(p4.x, E[j + 0], s0);
                s1 = fmaf(p4.y, E[j + 1], s1);
                s2 = fmaf(p4.z, E[j + 2], s2);
                s3 = fmaf(p4.w, E[j + 3], s3);
            }
            a = m + logf((s0 + s1) + (s2 + s3)) + sf_t;
            alpha_out[t * NS + k] = a;
        }
    }

    // log_partition = logsumexp_k(alpha_{T-1})
    float v = act ? a : -FLT_MAX;
#pragma unroll
    for (int o = 16; o > 0; o >>= 1)
        v = fmaxf(v, __shfl_xor_sync(0xffffffffu, v, o));
    if (lane == 0) sh_m[0][wid] = v;
    __syncthreads();
    float m = fmaxf(sh_m[0][0], sh_m[0][1]);
    float pe = act ? expf(a - m) : 0.f;
#pragma unroll
    for (int o = 16; o > 0; o >>= 1)
        pe += __shfl_xor_sync(0xffffffffu, pe, o);
    if (lane == 0) sh_p[0][wid] = pe;
    __syncthreads();
    if (tid == 0) out[b] = m + logf(sh_p[0][0] + sh_p[0][1]);
}

// ---------------- launch ----------------------------------------------------
extern "C" void kernel_launch(void* const* d_in, const int* in_sizes, int n_in,
                              void* d_out, int out_size) {
    const float* feat = (const float*)d_in[0];  // (256,512,1024)
    const float* sw   = (const float*)d_in[1];  // (48,1024)
    const float* sb   = (const float*)d_in[2];  // (48,)
    const float* tw   = (const float*)d_in[3];  // (48,48)
    const float* tb   = (const float*)d_in[4];  // (48,48)
    float* out = (float*)d_out;                 // [logpart(256) | alpha(256*512*48)]

    dim3 sgrid(NF / 256, NB);
    stats_kernel<<<sgrid, 256>>>(feat);
    gemm_kernel<<<NM / 128, 128>>>(feat, sw, sb);
    crf_kernel<<<NB, 64>>>(tw, tb, out);
}